// round 14
// baseline (speedup 1.0000x reference)
#include <cuda_runtime.h>
#include <cuda_fp16.h>
#include <cstdint>
#include <math.h>

static constexpr int Nd   = 8192;
static constexpr int Bd   = 256;
static constexpr int NNZc = 16 * Nd;
static constexpr int SLOTS = 64;

// ---------------- device scratch (no allocation) ----------------
__device__ __align__(1024) __half g_xth[Nd * Bd];       // x^T [N,B] fp16
__device__ __align__(1024) __half g_a0h[Bd * Nd];       // activations fp16 [B,N]
__device__ __align__(1024) __half g_h1h[Bd * Nd];
__device__ __align__(1024) __half g_h2h[Bd * Nd];
__device__ __align__(1024) float  g_part[128 * 16384];  // K-split partials, 8 MB
__device__ int   g_flag[128];
__device__ int   g_cnt[Nd];
__device__ __align__(1024) int2 g_cv[Nd * SLOTS];

// ---------------- helpers ----------------
__device__ __forceinline__ uint32_t smem_to_u32(const void* p) {
    uint32_t a;
    asm("{ .reg .u64 t; cvta.to.shared.u64 t, %1; cvt.u32.u64 %0, t; }" : "=r"(a) : "l"(p));
    return a;
}

__device__ __forceinline__ float selu_f(float x) {
    const float kS = 1.0507009873554805f;
    const float kA = 1.6732632423543772f;
    return x > 0.f ? kS * x : kS * kA * expm1f(x);
}

// A tile: 128 rows x 32 halves packed as 64 x 128B rows, SW128 (proven in R7)
__device__ __forceinline__ uint32_t swzA(uint32_t r, uint32_t c) {
    uint32_t byte = (r >> 1) * 128u + (r & 1u) * 64u + c * 2u;
    return byte ^ ((byte >> 3) & 0x70u);
}
// B tile: 128 rows x 32 fp32 = 128B rows, SW128 (proven in R7)
__device__ __forceinline__ uint32_t swzB(uint32_t r, uint32_t cw) {
    uint32_t byte = r * 128u + cw * 4u;
    return byte ^ ((byte >> 3) & 0x70u);
}

#define CP_ASYNC16(dst, src) \
    asm volatile("cp.async.cg.shared.global [%0], [%1], 16;" :: "r"(dst), "l"(src) : "memory")
#define CP_COMMIT() asm volatile("cp.async.commit_group;" ::: "memory")
#define CP_WAIT2()  asm volatile("cp.async.wait_group 2;" ::: "memory")

#define LDMATRIX_X4(r0, r1, r2, r3, addr) \
    asm volatile("ldmatrix.sync.aligned.m8n8.x4.shared.b16 {%0,%1,%2,%3}, [%4];" \
        : "=r"(r0), "=r"(r1), "=r"(r2), "=r"(r3) : "r"(addr))

#define MMA16816(d, a, b0, b1) \
    asm volatile("mma.sync.aligned.m16n8k16.row.col.f32.f16.f16.f32 " \
        "{%0,%1,%2,%3}, {%4,%5,%6,%7}, {%8,%9}, {%0,%1,%2,%3};" \
        : "+f"((d)[0]), "+f"((d)[1]), "+f"((d)[2]), "+f"((d)[3]) \
        : "r"((a)[0]), "r"((a)[1]), "r"((a)[2]), "r"((a)[3]), "r"(b0), "r"(b1))

// ---------------- sparse pipeline (3 launches) ----------------
__global__ void __launch_bounds__(256, 2) fused_prep_kernel(const float* __restrict__ x) {
    if (blockIdx.x < 2048) {
        __shared__ float t[32][33];
        int nb = (blockIdx.x & 255) * 32, bb = (blockIdx.x >> 8) * 32;
        int tx = threadIdx.x & 31, ty = threadIdx.x >> 5;
#pragma unroll
        for (int i = 0; i < 32; i += 8)
            t[ty + i][tx] = x[(size_t)(bb + ty + i) * Nd + nb + tx];
        __syncthreads();
#pragma unroll
        for (int i = 0; i < 32; i += 8)
            g_xth[(size_t)(nb + ty + i) * Bd + bb + tx] = __float2half_rn(t[tx][ty + i]);
    } else {
#pragma unroll
        for (int i = 0; i < Nd / 256; i++) g_cnt[threadIdx.x + i * 256] = 0;
    }
}

__global__ void build_kernel(const int* __restrict__ rows, const int* __restrict__ cols,
                             const float* __restrict__ vals) {
    for (int i = blockIdx.x * blockDim.x + threadIdx.x; i < NNZc; i += gridDim.x * blockDim.x) {
        int r = rows[i];
        int p = atomicAdd(&g_cnt[r], 1);
        g_cv[r * SLOTS + p] = make_int2(cols[i], __float_as_int(vals[i]));
    }
}

__global__ void spmv_kernel(const float* __restrict__ bc, const float* __restrict__ flag) {
    int row = blockIdx.x * 8 + (threadIdx.x >> 5);
    int lane = threadIdx.x & 31;
    int n = g_cnt[row];
    const int2* cv = g_cv + row * SLOTS;
    const __half* xbh = g_xth + lane * 8;
    float a0 = 0.f, a1 = 0.f, a2 = 0.f, a3 = 0.f, a4 = 0.f, a5 = 0.f, a6 = 0.f, a7 = 0.f;
    if (n > 0) {
        int2 c = cv[0];
        uint4 raw = *(const uint4*)(xbh + (size_t)c.x * Bd);
        for (int j = 0; j < n; j++) {
            float v = __int_as_float(c.y);
            int2 cn = c; uint4 rn = raw;
            if (j + 1 < n) {
                cn = cv[j + 1];
                rn = *(const uint4*)(xbh + (size_t)cn.x * Bd);
            }
            __half2* h = (__half2*)&raw;
            float2 p0 = __half22float2(h[0]);
            float2 p1 = __half22float2(h[1]);
            float2 p2 = __half22float2(h[2]);
            float2 p3 = __half22float2(h[3]);
            a0 += v * p0.x; a1 += v * p0.y; a2 += v * p1.x; a3 += v * p1.y;
            a4 += v * p2.x; a5 += v * p2.y; a6 += v * p3.x; a7 += v * p3.y;
            c = cn; raw = rn;
        }
    }
    float bcv = bc[row], fl = flag[row];
    float r[8] = {a0, a1, a2, a3, a4, a5, a6, a7};
#pragma unroll
    for (int i = 0; i < 8; i++)
        g_a0h[(size_t)(lane * 8 + i) * Nd + row] = __float2half_rn(bcv + r[i] * fl);
}

// ---------------- fp16 mma.sync GEMM: K-split 2, occupancy 2 ----------------
static constexpr int NSTAGE      = 4;
static constexpr int A_BYTES     = 8192;    // 128 x 32 halves
static constexpr int B_BYTES     = 16384;   // 128 x 32 fp32
static constexpr int STAGE_BYTES = A_BYTES + B_BYTES;       // 24 KB
static constexpr int GEMM_SMEM   = NSTAGE * STAGE_BYTES;    // 96 KB -> 2 CTAs/SM
static constexpr int KT_PER      = 128;     // 128 k32-tiles per CTA (K/2)

__device__ __forceinline__ void issue_stage(uint32_t sbase, int buf,
                                            const __half* At, const float* Wt,
                                            int k0, int tid) {
    uint32_t st = sbase + buf * STAGE_BYTES;
    // A: 512 x 16B chunks (row = 64B = 4 chunks)
#pragma unroll
    for (int i = 0; i < 2; i++) {
        int id = tid + i * 256;
        int r = id >> 2, c16 = id & 3;
        const __half* src = At + (size_t)r * Nd + k0 + c16 * 8;
        CP_ASYNC16(st + swzA(r, c16 * 8), src);
    }
    // B: 1024 x 16B chunks (row = 128B = 8 chunks), fp32
#pragma unroll
    for (int i = 0; i < 4; i++) {
        int id = tid + i * 256;
        int r = id >> 3, ch = id & 7;
        const float* src = Wt + (size_t)r * Nd + k0 + ch * 4;
        CP_ASYNC16(st + A_BYTES + swzB(r, ch * 4), src);
    }
}

__global__ void __launch_bounds__(256, 2)
gemm_f16_kernel(const __half* __restrict__ Ag, const float* __restrict__ Wg,
                const float* __restrict__ bias,
                const float* __restrict__ bc, const float* __restrict__ flag,
                void* __restrict__ outv, int mode, int layer)
{
    extern __shared__ char smem[];
    uint32_t sb = smem_to_u32(smem);
    int tid = threadIdx.x, lane = tid & 31, w = tid >> 5;
    int wm = w & 1, wn = w >> 1;                 // warp tile 64 x 32
    int pair = blockIdx.x >> 1;
    int ksplit = blockIdx.x & 1;
    int mtile = pair & 1, ntile = pair >> 1;

    const __half* At = Ag + (size_t)(mtile * 128) * Nd;
    const float*  Wt = Wg + (size_t)(ntile * 128) * Nd;
    const int kbase = ksplit * (Nd / 2);

    float acc[4][4][4];
#pragma unroll
    for (int a = 0; a < 4; a++)
#pragma unroll
        for (int b = 0; b < 4; b++)
#pragma unroll
            for (int c = 0; c < 4; c++) acc[a][b][c] = 0.f;

#pragma unroll
    for (int s = 0; s < NSTAGE - 1; s++) {
        issue_stage(sb, s, At, Wt, kbase + s * 32, tid);
        CP_COMMIT();
    }

    uint32_t ar[4][4], b0r[4], b1r[4];
#pragma unroll 1
    for (int t = 0; t < KT_PER; t++) {
        CP_WAIT2();          // committed 3+t, allow 2 outstanding -> stage t ready
        __syncthreads();     // visibility; stage t-1 fully consumed
        if (t + 3 < KT_PER)
            issue_stage(sb, (t + 3) % NSTAGE, At, Wt, kbase + (t + 3) * 32, tid);
        CP_COMMIT();

        uint32_t aB = sb + (t % NSTAGE) * STAGE_BYTES;
        uint32_t bB = aB + A_BYTES;
#pragma unroll
        for (int ks = 0; ks < 2; ks++) {
            uint32_t acol = ks * 16 + (lane >> 4) * 8;
#pragma unroll
            for (int mf = 0; mf < 4; mf++) {
                uint32_t row = wm * 64 + mf * 16 + (lane & 15);
                LDMATRIX_X4(ar[mf][0], ar[mf][1], ar[mf][2], ar[mf][3], aB + swzA(row, acol));
            }
            uint32_t nrow = wn * 32 + (lane >> 2);
            uint32_t clo = ks * 16 + (lane & 3) * 2;
#pragma unroll
            for (int nf = 0; nf < 4; nf++) {
                uint32_t r = nrow + nf * 8;
                float2 lo = *(const float2*)(smem + (bB - sb) + swzB(r, clo));
                float2 hi = *(const float2*)(smem + (bB - sb) + swzB(r, clo + 8));
                __half2 h0 = __floats2half2_rn(lo.x, lo.y);
                __half2 h1 = __floats2half2_rn(hi.x, hi.y);
                b0r[nf] = *(uint32_t*)&h0;
                b1r[nf] = *(uint32_t*)&h1;
            }
#pragma unroll
            for (int mf = 0; mf < 4; mf++)
#pragma unroll
                for (int nf = 0; nf < 4; nf++)
                    MMA16816(acc[mf][nf], ar[mf], b0r[nf], b1r[nf]);
        }
    }

    // ---- K-split pairing ----
    float* pp = g_part + (size_t)pair * 16384;   // 128x128 local tile
    if (ksplit == 1) {
        // producer: store raw partials, release flag
#pragma unroll
        for (int mf = 0; mf < 4; mf++)
#pragma unroll
            for (int nf = 0; nf < 4; nf++) {
                int lr = wm * 64 + mf * 16 + (lane >> 2);
                int lc = wn * 32 + nf * 8 + (lane & 3) * 2;
                *(float2*)(pp + lr * 128 + lc) = make_float2(acc[mf][nf][0], acc[mf][nf][1]);
                *(float2*)(pp + (lr + 8) * 128 + lc) = make_float2(acc[mf][nf][2], acc[mf][nf][3]);
            }
        __syncthreads();
        if (tid == 0) {
            __threadfence();
            atomicExch(&g_flag[pair], layer);
        }
    } else {
        // consumer: wait for partner, combine, epilogue
        if (tid == 0) {
            while (atomicAdd(&g_flag[pair], 0) < layer) __nanosleep(64);
        }
        __syncthreads();
        __threadfence();
#pragma unroll
        for (int mf = 0; mf < 4; mf++) {
#pragma unroll
            for (int nf = 0; nf < 4; nf++) {
                int lr = wm * 64 + mf * 16 + (lane >> 2);
                int lc = wn * 32 + nf * 8 + (lane & 3) * 2;
                float2 q0 = *(const float2*)(pp + lr * 128 + lc);
                float2 q1 = *(const float2*)(pp + (lr + 8) * 128 + lc);
                int r0 = mtile * 128 + lr;
                int c0 = ntile * 128 + lc;
                float b0 = __ldg(&bias[c0]), b1 = __ldg(&bias[c0 + 1]);
                float v00 = acc[mf][nf][0] + q0.x + b0, v01 = acc[mf][nf][1] + q0.y + b1;
                float v10 = acc[mf][nf][2] + q1.x + b0, v11 = acc[mf][nf][3] + q1.y + b1;
                if (mode == 0) {
                    __half2* o0 = (__half2*)((__half*)outv + (size_t)r0 * Nd + c0);
                    __half2* o1 = (__half2*)((__half*)outv + (size_t)(r0 + 8) * Nd + c0);
                    *o0 = __floats2half2_rn(selu_f(v00), selu_f(v01));
                    *o1 = __floats2half2_rn(selu_f(v10), selu_f(v11));
                } else {
                    float bc0 = __ldg(&bc[c0]), bc1 = __ldg(&bc[c0 + 1]);
                    float fl0 = __ldg(&flag[c0]), fl1 = __ldg(&flag[c0 + 1]);
                    float* o0 = (float*)outv + (size_t)r0 * Nd + c0;
                    float* o1 = (float*)outv + (size_t)(r0 + 8) * Nd + c0;
                    o0[0] = bc0 + v00 * fl0; o0[1] = bc1 + v01 * fl1;
                    o1[0] = bc0 + v10 * fl0; o1[1] = bc1 + v11 * fl1;
                }
            }
        }
    }
}

// ---------------- host ----------------
extern "C" void kernel_launch(void* const* d_in, const int* in_sizes, int n_in,
                              void* d_out, int out_size) {
    const float* x    = (const float*)d_in[0];
    const float* vals = (const float*)d_in[1];
    const float* bc   = (const float*)d_in[2];
    const float* flag = (const float*)d_in[3];
    const float* W1   = (const float*)d_in[4];
    const float* b1   = (const float*)d_in[5];
    const float* W2   = (const float*)d_in[6];
    const float* b2   = (const float*)d_in[7];
    const float* W3   = (const float*)d_in[8];
    const float* b3   = (const float*)d_in[9];
    const int*   rows = (const int*)d_in[10];
    const int*   cols = (const int*)d_in[11];

    void *pa0, *ph1, *ph2, *pflag;
    cudaGetSymbolAddress(&pa0, g_a0h);
    cudaGetSymbolAddress(&ph1, g_h1h);
    cudaGetSymbolAddress(&ph2, g_h2h);
    cudaGetSymbolAddress(&pflag, g_flag);

    cudaFuncSetAttribute(gemm_f16_kernel, cudaFuncAttributeMaxDynamicSharedMemorySize, GEMM_SMEM);

    cudaMemsetAsync(pflag, 0, 128 * sizeof(int));                         // flags -> 0 each replay
    fused_prep_kernel<<<2049, 256>>>(x);                                  // 1
    build_kernel<<<256, 256>>>(rows, cols, vals);                         // 2
    spmv_kernel<<<Nd / 8, 256>>>(bc, flag);                               // 3
    gemm_f16_kernel<<<256, 256, GEMM_SMEM>>>((__half*)pa0, W1, b1, bc, flag, ph1, 0, 1);
    gemm_f16_kernel<<<256, 256, GEMM_SMEM>>>((__half*)ph1, W2, b2, bc, flag, ph2, 0, 2);
    gemm_f16_kernel<<<256, 256, GEMM_SMEM>>>((__half*)ph2, W3, b3, bc, flag, d_out, 1, 3);
}

// round 15
// speedup vs baseline: 1.0594x; 1.0594x over previous
#include <cuda_runtime.h>
#include <cuda.h>
#include <cuda_fp16.h>
#include <cstdint>
#include <math.h>

static constexpr int Nd   = 8192;
static constexpr int Bd   = 256;
static constexpr int NNZc = 16 * Nd;
static constexpr int SLOTS = 64;

// ---------------- device scratch (no allocation) ----------------
__device__ __align__(1024) __half g_xth[Nd * Bd];       // x^T [N,B] fp16
__device__ __align__(1024) __half g_a0h[Bd * Nd];       // activations fp16 [B,N]
__device__ __align__(1024) __half g_h1h[Bd * Nd];
__device__ __align__(1024) __half g_h2h[Bd * Nd];
__device__ int   g_cnt[Nd];
__device__ __align__(1024) int2 g_cv[Nd * SLOTS];

// ---------------- helpers ----------------
__device__ __forceinline__ uint32_t smem_to_u32(const void* p) {
    uint32_t a;
    asm("{ .reg .u64 t; cvta.to.shared.u64 t, %1; cvt.u32.u64 %0, t; }" : "=r"(a) : "l"(p));
    return a;
}

__device__ __forceinline__ float selu_f(float x) {
    const float kS = 1.0507009873554805f;
    const float kA = 1.6732632423543772f;
    return x > 0.f ? kS * x : kS * kA * expm1f(x);
}

// canonical SW128 swizzle over 128B rows (matches TMA SWIZZLE_128B)
__device__ __forceinline__ uint32_t swzA64(uint32_t r, uint32_t c) {   // c in halves
    uint32_t byte = r * 128u + c * 2u;
    return byte ^ ((byte >> 3) & 0x70u);
}
__device__ __forceinline__ uint32_t swzB(uint32_t r, uint32_t cw) {    // cw in fp32 words
    uint32_t byte = r * 128u + cw * 4u;
    return byte ^ ((byte >> 3) & 0x70u);
}

#define LDMATRIX_X4(r0, r1, r2, r3, addr) \
    asm volatile("ldmatrix.sync.aligned.m8n8.x4.shared.b16 {%0,%1,%2,%3}, [%4];" \
        : "=r"(r0), "=r"(r1), "=r"(r2), "=r"(r3) : "r"(addr))

#define MMA16816(d, a, b0, b1) \
    asm volatile("mma.sync.aligned.m16n8k16.row.col.f32.f16.f16.f32 " \
        "{%0,%1,%2,%3}, {%4,%5,%6,%7}, {%8,%9}, {%0,%1,%2,%3};" \
        : "+f"((d)[0]), "+f"((d)[1]), "+f"((d)[2]), "+f"((d)[3]) \
        : "r"((a)[0]), "r"((a)[1]), "r"((a)[2]), "r"((a)[3]), "r"(b0), "r"(b1))

#define MBARRIER_INIT(a, c) \
    asm volatile("mbarrier.init.shared.b64 [%0], %1;" :: "r"((uint32_t)(a)), "r"((uint32_t)(c)) : "memory")
#define MBARRIER_EXPECT_TX(a, b) \
    asm volatile("mbarrier.arrive.expect_tx.shared.b64 _, [%0], %1;" :: "r"((uint32_t)(a)), "r"((uint32_t)(b)) : "memory")

#define MBAR_WAIT(a, ph) do { \
    uint32_t _m = (uint32_t)(a), _p = (uint32_t)(ph), _d; \
    asm volatile("{\n\t.reg .pred p;\n\t" \
        "mbarrier.try_wait.parity.acquire.cta.shared::cta.b64 p, [%1], %2;\n\t" \
        "selp.b32 %0, 1, 0, p;\n\t}" : "=r"(_d) : "r"(_m), "r"(_p) : "memory"); \
    if (!_d) { \
        asm volatile("{\n\t.reg .pred P1;\n\tWL_%=:\n\t" \
            "mbarrier.try_wait.parity.acquire.cta.shared::cta.b64 P1, [%0], %1, 0x989680;\n\t" \
            "@P1 bra.uni WD_%=;\n\tbra.uni WL_%=;\n\tWD_%=:\n\t}" \
            :: "r"(_m), "r"(_p) : "memory"); \
    } \
} while (0)

#define TMA2D(sa, map, cx, cy, mb) \
    asm volatile("cp.async.bulk.tensor.2d.shared::cta.global.tile.mbarrier::complete_tx::bytes " \
        "[%0], [%1, {%2, %3}], [%4];" \
        :: "r"((uint32_t)(sa)), "l"(map), "r"((int)(cx)), "r"((int)(cy)), "r"((uint32_t)(mb)) : "memory")

// ---------------- sparse pipeline (3 launches) ----------------
__global__ void __launch_bounds__(256, 2) fused_prep_kernel(const float* __restrict__ x) {
    if (blockIdx.x < 2048) {
        __shared__ float t[32][33];
        int nb = (blockIdx.x & 255) * 32, bb = (blockIdx.x >> 8) * 32;
        int tx = threadIdx.x & 31, ty = threadIdx.x >> 5;
#pragma unroll
        for (int i = 0; i < 32; i += 8)
            t[ty + i][tx] = x[(size_t)(bb + ty + i) * Nd + nb + tx];
        __syncthreads();
#pragma unroll
        for (int i = 0; i < 32; i += 8)
            g_xth[(size_t)(nb + ty + i) * Bd + bb + tx] = __float2half_rn(t[tx][ty + i]);
    } else {
#pragma unroll
        for (int i = 0; i < Nd / 256; i++) g_cnt[threadIdx.x + i * 256] = 0;
    }
}

__global__ void build_kernel(const int* __restrict__ rows, const int* __restrict__ cols,
                             const float* __restrict__ vals) {
    for (int i = blockIdx.x * blockDim.x + threadIdx.x; i < NNZc; i += gridDim.x * blockDim.x) {
        int r = rows[i];
        int p = atomicAdd(&g_cnt[r], 1);
        g_cv[r * SLOTS + p] = make_int2(cols[i], __float_as_int(vals[i]));
    }
}

__global__ void spmv_kernel(const float* __restrict__ bc, const float* __restrict__ flag) {
    int row = blockIdx.x * 8 + (threadIdx.x >> 5);
    int lane = threadIdx.x & 31;
    int n = g_cnt[row];
    const int2* cv = g_cv + row * SLOTS;
    const __half* xbh = g_xth + lane * 8;
    float a0 = 0.f, a1 = 0.f, a2 = 0.f, a3 = 0.f, a4 = 0.f, a5 = 0.f, a6 = 0.f, a7 = 0.f;
    if (n > 0) {
        int2 c = cv[0];
        uint4 raw = *(const uint4*)(xbh + (size_t)c.x * Bd);
        for (int j = 0; j < n; j++) {
            float v = __int_as_float(c.y);
            int2 cn = c; uint4 rn = raw;
            if (j + 1 < n) {
                cn = cv[j + 1];
                rn = *(const uint4*)(xbh + (size_t)cn.x * Bd);
            }
            __half2* h = (__half2*)&raw;
            float2 p0 = __half22float2(h[0]);
            float2 p1 = __half22float2(h[1]);
            float2 p2 = __half22float2(h[2]);
            float2 p3 = __half22float2(h[3]);
            a0 += v * p0.x; a1 += v * p0.y; a2 += v * p1.x; a3 += v * p1.y;
            a4 += v * p2.x; a5 += v * p2.y; a6 += v * p3.x; a7 += v * p3.y;
            c = cn; raw = rn;
        }
    }
    float bcv = bc[row], fl = flag[row];
    float r[8] = {a0, a1, a2, a3, a4, a5, a6, a7};
#pragma unroll
    for (int i = 0; i < 8; i++)
        g_a0h[(size_t)(lane * 8 + i) * Nd + row] = __float2half_rn(bcv + r[i] * fl);
}

// ---------------- TMA-fed fp16 mma.sync GEMM ----------------
// stage = [A 16KB (128m x 64k fp16)][B0 16KB (128n x 32k fp32)][B1 16KB]
static constexpr int NSTAGE      = 4;
static constexpr int A_BYTES     = 16384;
static constexpr int BSUB_BYTES  = 16384;
static constexpr int STAGE_BYTES = A_BYTES + 2 * BSUB_BYTES;    // 48 KB
static constexpr int SMEM_DATA   = 1024;                        // mbars below
static constexpr int GEMM_SMEM   = SMEM_DATA + NSTAGE * STAGE_BYTES;  // 197632
static constexpr int KTILES      = Nd / 64;  // 128

struct Frags {
    uint32_t ar[4][4];
    uint32_t b0r[4], b1r[4];
};

__device__ __forceinline__ void load_frags(Frags& f, const char* smem, uint32_t sb,
                                           int stage, int ks, int wm, int wn, int lane) {
    uint32_t aOff = SMEM_DATA + stage * STAGE_BYTES;
    uint32_t bOff = aOff + A_BYTES + (ks >> 1) * BSUB_BYTES;
    uint32_t acol = ks * 16 + (lane >> 4) * 8;
#pragma unroll
    for (int mf = 0; mf < 4; mf++) {
        uint32_t row = wm * 64 + mf * 16 + (lane & 15);
        LDMATRIX_X4(f.ar[mf][0], f.ar[mf][1], f.ar[mf][2], f.ar[mf][3],
                    sb + aOff + swzA64(row, acol));
    }
    uint32_t nrow = wn * 32 + (lane >> 2);
    uint32_t clo = (ks & 1) * 16 + (lane & 3) * 2;
#pragma unroll
    for (int nf = 0; nf < 4; nf++) {
        uint32_t r = nrow + nf * 8;
        float2 lo = *(const float2*)(smem + bOff + swzB(r, clo));
        float2 hi = *(const float2*)(smem + bOff + swzB(r, clo + 8));
        __half2 h0 = __floats2half2_rn(lo.x, lo.y);
        __half2 h1 = __floats2half2_rn(hi.x, hi.y);
        f.b0r[nf] = *(uint32_t*)&h0;
        f.b1r[nf] = *(uint32_t*)&h1;
    }
}

__device__ __forceinline__ void issue_stage_tma(uint32_t sb, int buf,
                                                const CUtensorMap* mA, const CUtensorMap* mB,
                                                int k0, int m0, int n0) {
    uint32_t bar = sb + buf * 8;
    uint32_t st = sb + SMEM_DATA + buf * STAGE_BYTES;
    MBARRIER_EXPECT_TX(bar, (uint32_t)STAGE_BYTES);
    TMA2D(st, mA, k0, m0, bar);                                   // A: 64k x 128m
    TMA2D(st + A_BYTES, mB, k0, n0, bar);                         // B0: 32k x 128n
    TMA2D(st + A_BYTES + BSUB_BYTES, mB, k0 + 32, n0, bar);       // B1
}

__global__ void __launch_bounds__(256, 1)
gemm_f16_kernel(const __grid_constant__ CUtensorMap tmA,
                const __grid_constant__ CUtensorMap tmB,
                const float* __restrict__ bias,
                const float* __restrict__ bc, const float* __restrict__ flag,
                void* __restrict__ outv, int mode)   // 0=selu->half, 1=addcmul->float
{
    extern __shared__ char smem[];
    uint32_t sb = smem_to_u32(smem);
    int tid = threadIdx.x, lane = tid & 31, w = tid >> 5;
    int wm = w & 1, wn = w >> 1;                       // warp tile 64x32
    int mtile = blockIdx.x & 1, ntile = blockIdx.x >> 1;
    int m0 = mtile * 128, n0 = ntile * 128;

    if (tid == 0) {
#pragma unroll
        for (int s = 0; s < NSTAGE; s++) MBARRIER_INIT(sb + s * 8, 1);
    }
    __syncthreads();

    if (tid == 0) {
#pragma unroll
        for (int s = 0; s < NSTAGE - 1; s++)           // stages 0,1,2
            issue_stage_tma(sb, s, &tmA, &tmB, s * 64, m0, n0);
    }

    float acc[4][4][4];
#pragma unroll
    for (int a = 0; a < 4; a++)
#pragma unroll
        for (int b = 0; b < 4; b++)
#pragma unroll
            for (int c = 0; c < 4; c++) acc[a][b][c] = 0.f;

    // stages 0 and 1 ready, preload f0 = (0,0)
    MBAR_WAIT(sb + 0 * 8, 0);
    MBAR_WAIT(sb + 1 * 8, 0);

    Frags f0, f1;
    load_frags(f0, smem, sb, 0, 0, wm, wn, lane);

#pragma unroll 1
    for (int t = 0; t < KTILES; t++) {
        // invariant at top: stages t and t+1 complete (mbar-waited)
        __syncthreads();     // all warps done reading stage t-1 (overwrite target)
        if (tid == 0 && t + 3 < KTILES)
            issue_stage_tma(sb, (t + 3) & 3, &tmA, &tmB, (t + 3) * 64, m0, n0);

        int st = t & 3;
        int sn = (t + 1) & 3;

        // ks=0: load (t,1) over MMA(t,0)
        load_frags(f1, smem, sb, st, 1, wm, wn, lane);
#pragma unroll
        for (int mf = 0; mf < 4; mf++)
#pragma unroll
            for (int nf = 0; nf < 4; nf++)
                MMA16816(acc[mf][nf], f0.ar[mf], f0.b0r[nf], f0.b1r[nf]);
        // ks=1: load (t,2) over MMA(t,1)
        load_frags(f0, smem, sb, st, 2, wm, wn, lane);
#pragma unroll
        for (int mf = 0; mf < 4; mf++)
#pragma unroll
            for (int nf = 0; nf < 4; nf++)
                MMA16816(acc[mf][nf], f1.ar[mf], f1.b0r[nf], f1.b1r[nf]);
        // ks=2: load (t,3) over MMA(t,2)
        load_frags(f1, smem, sb, st, 3, wm, wn, lane);
#pragma unroll
        for (int mf = 0; mf < 4; mf++)
#pragma unroll
            for (int nf = 0; nf < 4; nf++)
                MMA16816(acc[mf][nf], f0.ar[mf], f0.b0r[nf], f0.b1r[nf]);
        // ks=3: load (t+1,0) (stage t+1 already mbar-complete) over MMA(t,3)
        if (t + 1 < KTILES)
            load_frags(f0, smem, sb, sn, 0, wm, wn, lane);
#pragma unroll
        for (int mf = 0; mf < 4; mf++)
#pragma unroll
            for (int nf = 0; nf < 4; nf++)
                MMA16816(acc[mf][nf], f1.ar[mf], f1.b0r[nf], f1.b1r[nf]);

        // restore invariant for next iter: wait stage t+2 (issued at iter t-1)
        if (t + 2 < KTILES)
            MBAR_WAIT(sb + ((t + 2) & 3) * 8, ((t + 2) >> 2) & 1);
    }

#pragma unroll
    for (int mf = 0; mf < 4; mf++) {
#pragma unroll
        for (int nf = 0; nf < 4; nf++) {
            int r0 = m0 + wm * 64 + mf * 16 + (lane >> 2);
            int c0 = n0 + wn * 32 + nf * 8 + (lane & 3) * 2;
            float b0 = __ldg(&bias[c0]), b1 = __ldg(&bias[c0 + 1]);
            float v00 = acc[mf][nf][0] + b0, v01 = acc[mf][nf][1] + b1;
            float v10 = acc[mf][nf][2] + b0, v11 = acc[mf][nf][3] + b1;
            if (mode == 0) {
                __half2* o0 = (__half2*)((__half*)outv + (size_t)r0 * Nd + c0);
                __half2* o1 = (__half2*)((__half*)outv + (size_t)(r0 + 8) * Nd + c0);
                *o0 = __floats2half2_rn(selu_f(v00), selu_f(v01));
                *o1 = __floats2half2_rn(selu_f(v10), selu_f(v11));
            } else {
                float bc0 = __ldg(&bc[c0]), bc1 = __ldg(&bc[c0 + 1]);
                float fl0 = __ldg(&flag[c0]), fl1 = __ldg(&flag[c0 + 1]);
                float* o0 = (float*)outv + (size_t)r0 * Nd + c0;
                float* o1 = (float*)outv + (size_t)(r0 + 8) * Nd + c0;
                o0[0] = bc0 + v00 * fl0; o0[1] = bc1 + v01 * fl1;
                o1[0] = bc0 + v10 * fl0; o1[1] = bc1 + v11 * fl1;
            }
        }
    }
}

// ---------------- host ----------------
typedef CUresult (*PFN_enc)(CUtensorMap*, CUtensorMapDataType, cuuint32_t, void*,
                            const cuuint64_t*, const cuuint64_t*, const cuuint32_t*,
                            const cuuint32_t*, CUtensorMapInterleave, CUtensorMapSwizzle,
                            CUtensorMapL2promotion, CUtensorMapFloatOOBfill);

static void mk_map_f16(PFN_enc enc, CUtensorMap* m, void* ptr, uint64_t d1) {
    cuuint64_t dims[2]    = {(cuuint64_t)Nd, d1};
    cuuint64_t strides[1] = {(cuuint64_t)Nd * 2};
    cuuint32_t box[2]     = {64, 128};   // 128B x 128 rows
    cuuint32_t es[2]      = {1, 1};
    enc(m, CU_TENSOR_MAP_DATA_TYPE_FLOAT16, 2, ptr, dims, strides, box, es,
        CU_TENSOR_MAP_INTERLEAVE_NONE, CU_TENSOR_MAP_SWIZZLE_128B,
        CU_TENSOR_MAP_L2_PROMOTION_L2_128B, CU_TENSOR_MAP_FLOAT_OOB_FILL_NONE);
}
static void mk_map_f32(PFN_enc enc, CUtensorMap* m, void* ptr) {
    cuuint64_t dims[2]    = {(cuuint64_t)Nd, (cuuint64_t)Nd};
    cuuint64_t strides[1] = {(cuuint64_t)Nd * 4};
    cuuint32_t box[2]     = {32, 128};   // 128B x 128 rows
    cuuint32_t es[2]      = {1, 1};
    enc(m, CU_TENSOR_MAP_DATA_TYPE_FLOAT32, 2, ptr, dims, strides, box, es,
        CU_TENSOR_MAP_INTERLEAVE_NONE, CU_TENSOR_MAP_SWIZZLE_128B,
        CU_TENSOR_MAP_L2_PROMOTION_L2_128B, CU_TENSOR_MAP_FLOAT_OOB_FILL_NONE);
}

extern "C" void kernel_launch(void* const* d_in, const int* in_sizes, int n_in,
                              void* d_out, int out_size) {
    const float* x    = (const float*)d_in[0];
    const float* vals = (const float*)d_in[1];
    const float* bc   = (const float*)d_in[2];
    const float* flag = (const float*)d_in[3];
    const float* W1   = (const float*)d_in[4];
    const float* b1   = (const float*)d_in[5];
    const float* W2   = (const float*)d_in[6];
    const float* b2   = (const float*)d_in[7];
    const float* W3   = (const float*)d_in[8];
    const float* b3   = (const float*)d_in[9];
    const int*   rows = (const int*)d_in[10];
    const int*   cols = (const int*)d_in[11];

    void *pa0, *ph1, *ph2;
    cudaGetSymbolAddress(&pa0, g_a0h);
    cudaGetSymbolAddress(&ph1, g_h1h);
    cudaGetSymbolAddress(&ph2, g_h2h);

    void* fn = nullptr;
    cudaDriverEntryPointQueryResult qr;
    cudaGetDriverEntryPoint("cuTensorMapEncodeTiled", &fn, cudaEnableDefault, &qr);
    PFN_enc enc = (PFN_enc)fn;

    CUtensorMap mA1, mA2, mA3, mB1, mB2, mB3;
    mk_map_f16(enc, &mA1, pa0, Bd);
    mk_map_f16(enc, &mA2, ph1, Bd);
    mk_map_f16(enc, &mA3, ph2, Bd);
    mk_map_f32(enc, &mB1, (void*)W1);
    mk_map_f32(enc, &mB2, (void*)W2);
    mk_map_f32(enc, &mB3, (void*)W3);

    cudaFuncSetAttribute(gemm_f16_kernel, cudaFuncAttributeMaxDynamicSharedMemorySize, GEMM_SMEM);

    fused_prep_kernel<<<2049, 256>>>(x);                                  // 0
    build_kernel<<<256, 256>>>(rows, cols, vals);                         // 1
    spmv_kernel<<<Nd / 8, 256>>>(bc, flag);                               // 2
    gemm_f16_kernel<<<128, 256, GEMM_SMEM>>>(mA1, mB1, b1, bc, flag, ph1, 0);   // 3 <- ncu
    gemm_f16_kernel<<<128, 256, GEMM_SMEM>>>(mA2, mB2, b2, bc, flag, ph2, 0);   // 4
    gemm_f16_kernel<<<128, 256, GEMM_SMEM>>>(mA3, mB3, b3, bc, flag, d_out, 1); // 5
}